// round 13
// baseline (speedup 1.0000x reference)
#include <cuda_runtime.h>
#include <cuda_fp16.h>
#include <cstdint>

#define NN 100000
#define DF 128
#define MAXE 1600000

// ---------------- device scratch: FROZEN symbol set/sizes/order (guard-sensitive).
//   g_S : (half*)g_S = prescaled feature rows (pass1: x*dinv, pass2: S from GEMM1)
//   g_T : (int2*)g_T = staged decoded edges during CSR build;
//         (half*)g_T = fp16 aggregation result afterwards
//   g_esrc[0..NN) = CSR offset cursor (end-of-range after fill); g_esrc[NN] = alloc counter
//   g_edst[0..E)  = CSR source-index list bucketed by destination
static __device__ float g_S[(size_t)NN * DF];
static __device__ float g_T[(size_t)NN * DF];
static __device__ float g_deg[NN];
static __device__ float g_dinv[NN];
static __device__ int   g_esrc[MAXE];
static __device__ int   g_edst[MAXE];
static __device__ int   g_mode;                 // 0 = edges are int64, 1 = int32

// ---------------- mma helpers ----------------
__device__ __forceinline__ void ldsm_x4(unsigned* r, unsigned addr) {
    asm volatile("ldmatrix.sync.aligned.m8n8.x4.shared.b16 {%0,%1,%2,%3}, [%4];"
                 : "=r"(r[0]), "=r"(r[1]), "=r"(r[2]), "=r"(r[3]) : "r"(addr));
}
__device__ __forceinline__ void ldsm_x2_trans(unsigned* r, unsigned addr) {
    asm volatile("ldmatrix.sync.aligned.m8n8.x2.trans.shared.b16 {%0,%1}, [%2];"
                 : "=r"(r[0]), "=r"(r[1]) : "r"(addr));
}
__device__ __forceinline__ void mma16816(float* c, const unsigned* a, const unsigned* b) {
    asm volatile("mma.sync.aligned.m16n8k16.row.col.f32.f16.f16.f32 "
                 "{%0,%1,%2,%3}, {%4,%5,%6,%7}, {%8,%9}, {%0,%1,%2,%3};"
                 : "+f"(c[0]), "+f"(c[1]), "+f"(c[2]), "+f"(c[3])
                 : "r"(a[0]), "r"(a[1]), "r"(a[2]), "r"(a[3]), "r"(b[0]), "r"(b[1]));
}

// smem layout (bytes): As 128x136 half | Bs 128x136 half | Cs 128x132 f32
#define SM_AS 0
#define SM_BS 34816
#define SM_CS 69632
#define SM_TOTAL (69632 + 128 * 132 * 4)   // 137216

// ---------------- edge decode helper ----------------
__device__ __forceinline__ void decode_edge(const void* ei, int E, int i, int& s, int& d) {
    if (g_mode) {
        const int* p = (const int*)ei;
        s = p[i]; d = p[(size_t)E + i];
    } else {
        const long long* p = (const long long*)ei;
        s = (int)p[i]; d = (int)p[(size_t)E + i];
    }
}

// ---------------- setup: deg init + dtype detect (merged) ----------------
__global__ void k_init_detect(const long long* __restrict__ ei, int n, int E) {
    int i = blockIdx.x * blockDim.x + threadIdx.x;
    if (i < n) g_deg[i] = 1.0f;                 // self loop contributes 1
    if (i == 0) g_esrc[NN] = 0;                 // allocation counter
    if (blockIdx.x == 0) {                      // block-uniform branch
        __shared__ int flag;
        if (threadIdx.x == 0) flag = 0;
        __syncthreads();
        int m = min(1024, E);
        for (int j = threadIdx.x; j < m; j += blockDim.x) {
            long long v = ei[j];
            if (v < 0 || v >= (long long)n) flag = 1;
        }
        __syncthreads();
        if (threadIdx.x == 0) g_mode = flag;    // int32 data seen as int64 -> OOB
    }
}

// count + stage decoded (s,d) pairs into g_T (free until gather pass 1)
__global__ void k_count(const void* __restrict__ ei, int E) {
    int i = blockIdx.x * blockDim.x + threadIdx.x;
    if (i >= E) return;
    int s, d;
    decode_edge(ei, E, i, s, d);
    ((int2*)g_T)[i] = make_int2(s, d);
    atomicAdd(&g_deg[d], 1.0f);
}

// ---------------- alloc offsets + prep H rows (merged; n*32 threads) ----------------
__global__ void k_alloc_prep(const float* __restrict__ x, int n) {
    int i = blockIdx.x * blockDim.x + threadIdx.x;   // n*32 float4 chunks
    if (i >= n * 32) return;
    int row = i >> 5;
    float deg = g_deg[row];
    float dv = rsqrtf(deg);                     // recomputed per lane (cheap)
    if ((i & 31) == 0) {
        g_dinv[row] = dv;
        g_esrc[row] = atomicAdd(&g_esrc[NN], (int)deg - 1);  // disjoint ranges
    }
    float4 v = ((const float4*)x)[i];
    __half2 h0 = __floats2half2_rn(v.x * dv, v.y * dv);
    __half2 h1 = __floats2half2_rn(v.z * dv, v.w * dv);
    ((__half2*)g_S)[(size_t)i * 2]     = h0;
    ((__half2*)g_S)[(size_t)i * 2 + 1] = h1;
}

__global__ void k_fill(int E) {
    int i = blockIdx.x * blockDim.x + threadIdx.x;
    if (i >= E) return;
    int2 e = ((const int2*)g_T)[i];             // staged by k_count
    int pos = atomicAdd(&g_esrc[e.y], 1);       // cursor ends at range end
    g_edst[pos] = e.x;
}

// ---------------- gather: T16[v] = H[v] + sum_{s in N(v)} H[s];  H = (half*)g_S ----------
// One warp per node, 4 neighbors per step: lane group g=lane>>3 picks the neighbor,
// sub=lane&7 picks a 32B slice (2 x uint4) of the 256B row. 2 independent LDG.128/lane/step.
__device__ __forceinline__ void acc_u4(float* acc, uint4 v) {
    union { uint4 u; __half2 h[4]; } cv; cv.u = v;
    #pragma unroll
    for (int q = 0; q < 4; q++) {
        float2 f = __half22float2(cv.h[q]);
        acc[2 * q]     += f.x;
        acc[2 * q + 1] += f.y;
    }
}

__global__ void k_gather(int n) {
    int w = (blockIdx.x * blockDim.x + threadIdx.x) >> 5;
    if (w >= n) return;
    const int lane = threadIdx.x & 31;
    const int g4   = lane >> 3;                 // neighbor subgroup 0..3
    const int sub  = lane & 7;                  // 32B slice of row
    const int cnt  = (int)g_deg[w] - 1;
    const int base = g_esrc[w] - cnt;           // cursor was advanced to end
    const uint4* H16 = (const uint4*)g_S;       // row = 16 uint4

    float acc[16];
    #pragma unroll
    for (int q = 0; q < 16; q++) acc[q] = 0.0f;

    if (g4 == 0) {                              // self term once
        acc_u4(acc,     H16[(size_t)w * 16 + sub * 2]);
        acc_u4(acc + 8, H16[(size_t)w * 16 + sub * 2 + 1]);
    }

    for (int j0 = 0; j0 < cnt; j0 += 32) {
        int s = 0;
        if (j0 + lane < cnt) s = g_edst[base + j0 + lane];
        int m = cnt - j0; if (m > 32) m = 32;
        int tmax = (m + 3) >> 2;
        #pragma unroll 2
        for (int t = 0; t < tmax; t++) {
            int src = 4 * t + g4;
            int sv = __shfl_sync(0xffffffffu, s, src);
            uint4 v0 = H16[(size_t)sv * 16 + sub * 2];      // sv==0 safe when invalid
            uint4 v1 = H16[(size_t)sv * 16 + sub * 2 + 1];
            if (j0 + src < cnt) { acc_u4(acc, v0); acc_u4(acc + 8, v1); }
        }
    }

    // combine the 4 lane groups (lanes with equal sub hold the same 16 columns)
    #pragma unroll
    for (int q = 0; q < 16; q++) {
        acc[q] += __shfl_xor_sync(0xffffffffu, acc[q], 8);
        acc[q] += __shfl_xor_sync(0xffffffffu, acc[q], 16);
    }

    if (g4 == 0) {
        union { uint4 u; __half2 h[4]; } pk;
        #pragma unroll
        for (int q = 0; q < 4; q++)
            pk.h[q] = __floats2half2_rn(acc[2 * q], acc[2 * q + 1]);
        ((uint4*)g_T)[(size_t)w * 16 + sub * 2] = pk.u;
        #pragma unroll
        for (int q = 0; q < 4; q++)
            pk.h[q] = __floats2half2_rn(acc[8 + 2 * q], acc[8 + 2 * q + 1]);
        ((uint4*)g_T)[(size_t)w * 16 + sub * 2 + 1] = pk.u;
    }
}

// ---------------- shared mma core: Cs = A(TxW) for one 128x128 tile ----------------
__device__ __forceinline__ void mma_tile(char* smx, int row0, int nrows, int tid) {
    __half* As = (__half*)(smx + SM_AS);
    float*  Cs = (float*)(smx + SM_CS);

    const uint4* Tp = (const uint4*)g_T;
    for (int i = tid; i < 128 * 16; i += 256) {
        int r = i >> 4, ch = i & 15;
        int row = row0 + r;
        uint4 v = make_uint4(0, 0, 0, 0);
        if (row < nrows) v = Tp[(size_t)row * 16 + ch];
        *(uint4*)&As[r * 136 + ch * 8] = v;
    }
    __syncthreads();

    const int lane = tid & 31, warp = tid >> 5;
    const int m0 = warp * 16;
    float c[16][4];
    #pragma unroll
    for (int j = 0; j < 16; j++)
        #pragma unroll
        for (int q = 0; q < 4; q++) c[j][q] = 0.0f;

    unsigned a_base = (unsigned)__cvta_generic_to_shared(smx + SM_AS);
    unsigned b_base = (unsigned)__cvta_generic_to_shared(smx + SM_BS);
    unsigned a_addr = a_base + ((m0 + (lane & 15)) * 136 + (lane >> 4) * 8) * 2;

    #pragma unroll
    for (int k0 = 0; k0 < 128; k0 += 16) {
        unsigned a[4];
        ldsm_x4(a, a_addr + k0 * 2);
        unsigned brow = b_base + ((k0 + (lane & 15)) * 136) * 2;
        #pragma unroll
        for (int j = 0; j < 16; j++) {
            unsigned b[2];
            ldsm_x2_trans(b, brow + j * 16);
            mma16816(c[j], a, b);
        }
    }

    const int r1 = m0 + (lane >> 2);
    const int cb = 2 * (lane & 3);
    #pragma unroll
    for (int j = 0; j < 16; j++) {
        *(float2*)&Cs[r1 * 132 + j * 8 + cb]       = make_float2(c[j][0], c[j][1]);
        *(float2*)&Cs[(r1 + 8) * 132 + j * 8 + cb] = make_float2(c[j][2], c[j][3]);
    }
    __syncthreads();
}

// ---------------- GEMM 1: (half*)g_S = relu(dinv * (T @ W1) + b1) * dinv ----------------
__global__ __launch_bounds__(256)
void k_gemm_hs(const float* __restrict__ W, const float* __restrict__ bias, int nrows) {
    extern __shared__ char smx[];
    __half* Bs = (__half*)(smx + SM_BS);
    float*  Cs = (float*)(smx + SM_CS);
    const int tid  = threadIdx.x;
    const int row0 = blockIdx.x * 128;

    for (int i = tid; i < 128 * 32; i += 256) {
        int k = i >> 5, c4 = (i & 31) * 4;
        float4 w = *(const float4*)&W[k * 128 + c4];
        *(__half2*)&Bs[k * 136 + c4]     = __floats2half2_rn(w.x, w.y);
        *(__half2*)&Bs[k * 136 + c4 + 2] = __floats2half2_rn(w.z, w.w);
    }
    mma_tile(smx, row0, nrows, tid);

    const int tx = tid & 15, ty = tid >> 4, col = tx * 8;
    #pragma unroll
    for (int i = 0; i < 8; i++) {
        int row = row0 + ty * 8 + i;
        if (row < nrows) {
            float d = g_dinv[row];
            float4 v0 = *(float4*)&Cs[(ty * 8 + i) * 132 + col];
            float4 v1 = *(float4*)&Cs[(ty * 8 + i) * 132 + col + 4];
            float o[8] = {v0.x, v0.y, v0.z, v0.w, v1.x, v1.y, v1.z, v1.w};
            #pragma unroll
            for (int j = 0; j < 8; j++)
                o[j] = fmaxf(fmaf(o[j], d, bias[col + j]), 0.0f) * d;
            union { __half2 h[4]; uint4 u; } pk;
            pk.h[0] = __floats2half2_rn(o[0], o[1]);
            pk.h[1] = __floats2half2_rn(o[2], o[3]);
            pk.h[2] = __floats2half2_rn(o[4], o[5]);
            pk.h[3] = __floats2half2_rn(o[6], o[7]);
            *(uint4*)((__half*)g_S + (size_t)row * 128 + col) = pk.u;
        }
    }
}

// ---------------- GEMM 2: [mu | logvar] = dinv * (T @ [Wmu|Wlv]) + [bmu|blv] ----------------
__global__ __launch_bounds__(256)
void k_gemm_out(const float* __restrict__ Wmu, const float* __restrict__ Wlv,
                const float* __restrict__ bmu, const float* __restrict__ blv,
                float* __restrict__ out_mu, float* __restrict__ out_lv, int nrows) {
    extern __shared__ char smx[];
    __half* Bs = (__half*)(smx + SM_BS);
    float*  Cs = (float*)(smx + SM_CS);
    const int tid  = threadIdx.x;
    const int row0 = blockIdx.x * 128;

    for (int i = tid; i < 128 * 32; i += 256) {
        int k = i >> 5, c4 = (i & 31) * 4;
        float4 w = (c4 < 64) ? *(const float4*)&Wmu[k * 64 + c4]
                             : *(const float4*)&Wlv[k * 64 + (c4 - 64)];
        *(__half2*)&Bs[k * 136 + c4]     = __floats2half2_rn(w.x, w.y);
        *(__half2*)&Bs[k * 136 + c4 + 2] = __floats2half2_rn(w.z, w.w);
    }
    mma_tile(smx, row0, nrows, tid);

    const int tx = tid & 15, ty = tid >> 4, col = tx * 8;
    const bool is_mu = (col < 64);
    const float* bias = is_mu ? bmu : blv;
    float* outp = is_mu ? out_mu : out_lv;
    const int ocol = is_mu ? col : (col - 64);

    #pragma unroll
    for (int i = 0; i < 8; i++) {
        int row = row0 + ty * 8 + i;
        if (row < nrows) {
            float d = g_dinv[row];
            float4 v0 = *(float4*)&Cs[(ty * 8 + i) * 132 + col];
            float4 v1 = *(float4*)&Cs[(ty * 8 + i) * 132 + col + 4];
            float o[8] = {v0.x, v0.y, v0.z, v0.w, v1.x, v1.y, v1.z, v1.w};
            #pragma unroll
            for (int j = 0; j < 8; j++)
                o[j] = fmaf(o[j], d, bias[ocol + j]);
            float4* Op = (float4*)&outp[(size_t)row * 64 + ocol];
            Op[0] = make_float4(o[0], o[1], o[2], o[3]);
            Op[1] = make_float4(o[4], o[5], o[6], o[7]);
        }
    }
}

// ---------------- launch ----------------
extern "C" void kernel_launch(void* const* d_in, const int* in_sizes, int n_in,
                              void* d_out, int out_size) {
    const float* x   = (const float*)d_in[0];
    const void*  ei  = d_in[1];
    const float* W1  = (const float*)d_in[2];
    const float* b1  = (const float*)d_in[3];
    const float* Wmu = (const float*)d_in[4];
    const float* bmu = (const float*)d_in[5];
    const float* Wlv = (const float*)d_in[6];
    const float* blv = (const float*)d_in[7];
    float* out = (float*)d_out;

    const int n = in_sizes[0] / DF;     // 100000
    const int E = in_sizes[1] / 2;      // 1600000

    cudaFuncSetAttribute(k_gemm_hs,  cudaFuncAttributeMaxDynamicSharedMemorySize, SM_TOTAL);
    cudaFuncSetAttribute(k_gemm_out, cudaFuncAttributeMaxDynamicSharedMemorySize, SM_TOTAL);

    // CSR build (per call; kernel_launch must be self-contained & deterministic)
    k_init_detect<<<(n + 255) / 256, 256>>>((const long long*)ei, n, E);
    k_count<<<(E + 255) / 256, 256>>>(ei, E);
    k_alloc_prep<<<(n * 32 + 255) / 256, 256>>>(x, n);
    k_fill<<<(E + 255) / 256, 256>>>(E);

    const int gwblocks = (n * 32 + 255) / 256;   // one warp per node
    const int gblocks  = (n + 127) / 128;

    // Layer 1: T16 = Aggr(H); S(half) = relu(dinv*(T@W1)+b1)*dinv
    k_gather<<<gwblocks, 256>>>(n);
    k_gemm_hs<<<gblocks, 256, SM_TOTAL>>>(W1, b1, n);

    // Layers 2+3 share one aggregation; fused [Wmu|Wlv] GEMM writes mu and logvar
    k_gather<<<gwblocks, 256>>>(n);
    k_gemm_out<<<gblocks, 256, SM_TOTAL>>>(Wmu, Wlv, bmu, blv, out, out + (size_t)n * 64, n);
}

// round 14
// speedup vs baseline: 1.0408x; 1.0408x over previous
#include <cuda_runtime.h>
#include <cuda_fp16.h>
#include <cstdint>

#define NN 100000
#define DF 128
#define MAXE 1600000

// ---------------- device scratch: FROZEN symbol set/sizes/order (guard-sensitive).
//   g_S : (half*)g_S = prescaled feature rows (pass1: x*dinv, pass2: S from GEMM1)
//   g_T : (int2*)g_T = staged decoded edges during CSR build;
//         (half*)g_T = fp16 aggregation result afterwards
//   g_esrc[0..NN) = CSR offset cursor (end-of-range after fill); g_esrc[NN] = alloc counter
//   g_edst[0..E)  = CSR source-index list bucketed by destination
static __device__ float g_S[(size_t)NN * DF];
static __device__ float g_T[(size_t)NN * DF];
static __device__ float g_deg[NN];
static __device__ float g_dinv[NN];
static __device__ int   g_esrc[MAXE];
static __device__ int   g_edst[MAXE];
static __device__ int   g_mode;                 // 0 = edges are int64, 1 = int32

// ---------------- mma helpers ----------------
__device__ __forceinline__ void ldsm_x4(unsigned* r, unsigned addr) {
    asm volatile("ldmatrix.sync.aligned.m8n8.x4.shared.b16 {%0,%1,%2,%3}, [%4];"
                 : "=r"(r[0]), "=r"(r[1]), "=r"(r[2]), "=r"(r[3]) : "r"(addr));
}
__device__ __forceinline__ void ldsm_x2_trans(unsigned* r, unsigned addr) {
    asm volatile("ldmatrix.sync.aligned.m8n8.x2.trans.shared.b16 {%0,%1}, [%2];"
                 : "=r"(r[0]), "=r"(r[1]) : "r"(addr));
}
__device__ __forceinline__ void mma16816(float* c, const unsigned* a, const unsigned* b) {
    asm volatile("mma.sync.aligned.m16n8k16.row.col.f32.f16.f16.f32 "
                 "{%0,%1,%2,%3}, {%4,%5,%6,%7}, {%8,%9}, {%0,%1,%2,%3};"
                 : "+f"(c[0]), "+f"(c[1]), "+f"(c[2]), "+f"(c[3])
                 : "r"(a[0]), "r"(a[1]), "r"(a[2]), "r"(a[3]), "r"(b[0]), "r"(b[1]));
}

// smem layout (bytes): As 128x136 half | Bs 128x136 half | Cs 128x132 f32
#define SM_AS 0
#define SM_BS 34816
#define SM_CS 69632
#define SM_TOTAL (69632 + 128 * 132 * 4)   // 137216

// ---------------- edge decode helper ----------------
__device__ __forceinline__ void decode_edge(const void* ei, int E, int i, int& s, int& d) {
    if (g_mode) {
        const int* p = (const int*)ei;
        s = p[i]; d = p[(size_t)E + i];
    } else {
        const long long* p = (const long long*)ei;
        s = (int)p[i]; d = (int)p[(size_t)E + i];
    }
}

// ---------------- setup: deg init + dtype detect (merged) ----------------
__global__ void k_init_detect(const long long* __restrict__ ei, int n, int E) {
    int i = blockIdx.x * blockDim.x + threadIdx.x;
    if (i < n) g_deg[i] = 1.0f;                 // self loop contributes 1
    if (i == 0) g_esrc[NN] = 0;                 // allocation counter
    if (blockIdx.x == 0) {                      // block-uniform branch
        __shared__ int flag;
        if (threadIdx.x == 0) flag = 0;
        __syncthreads();
        int m = min(1024, E);
        for (int j = threadIdx.x; j < m; j += blockDim.x) {
            long long v = ei[j];
            if (v < 0 || v >= (long long)n) flag = 1;
        }
        __syncthreads();
        if (threadIdx.x == 0) g_mode = flag;    // int32 data seen as int64 -> OOB
    }
}

// count + stage decoded (s,d) pairs into g_T (free until gather pass 1)
__global__ void k_count(const void* __restrict__ ei, int E) {
    int i = blockIdx.x * blockDim.x + threadIdx.x;
    if (i >= E) return;
    int s, d;
    decode_edge(ei, E, i, s, d);
    ((int2*)g_T)[i] = make_int2(s, d);
    atomicAdd(&g_deg[d], 1.0f);
}

// ---------------- alloc offsets + prep H rows (merged; n*32 threads) ----------------
__global__ void k_alloc_prep(const float* __restrict__ x, int n) {
    int i = blockIdx.x * blockDim.x + threadIdx.x;   // n*32 float4 chunks
    if (i >= n * 32) return;
    int row = i >> 5;
    float deg = g_deg[row];
    float dv = rsqrtf(deg);                     // recomputed per lane (cheap)
    if ((i & 31) == 0) {
        g_dinv[row] = dv;
        g_esrc[row] = atomicAdd(&g_esrc[NN], (int)deg - 1);  // disjoint ranges
    }
    float4 v = ((const float4*)x)[i];
    __half2 h0 = __floats2half2_rn(v.x * dv, v.y * dv);
    __half2 h1 = __floats2half2_rn(v.z * dv, v.w * dv);
    ((__half2*)g_S)[(size_t)i * 2]     = h0;
    ((__half2*)g_S)[(size_t)i * 2 + 1] = h1;
}

__global__ void k_fill(int E) {
    int i = blockIdx.x * blockDim.x + threadIdx.x;
    if (i >= E) return;
    int2 e = ((const int2*)g_T)[i];             // staged by k_count
    int pos = atomicAdd(&g_esrc[e.y], 1);       // cursor ends at range end
    g_edst[pos] = e.x;
}

// ---------------- gather: T16[v] = H[v] + sum_{s in N(v)} H[s];  H = (half*)g_S ----------
// R10 pair-split version (known-good): lanes 0-15 even neighbors, 16-31 odd;
// each lane covers 16 bytes (8 halves) of the 256B row. acc[8] keeps regs low.
__device__ __forceinline__ void acc_row16(float* acc, uint4 v) {
    union { uint4 u; __half2 h[4]; } cv; cv.u = v;
    #pragma unroll
    for (int q = 0; q < 4; q++) {
        float2 f = __half22float2(cv.h[q]);
        acc[2 * q]     += f.x;
        acc[2 * q + 1] += f.y;
    }
}

__global__ void k_gather(int n) {
    int w = (blockIdx.x * blockDim.x + threadIdx.x) >> 5;
    if (w >= n) return;
    const int lane = threadIdx.x & 31;
    const int hf   = lane >> 4;                 // 0: even neighbors, 1: odd
    const int sub  = lane & 15;                 // 16B chunk within row
    const int cnt  = (int)g_deg[w] - 1;
    const int base = g_esrc[w] - cnt;           // cursor was advanced to end
    const uint4* H16 = (const uint4*)g_S;       // row = 16 uint4

    float acc[8];
    #pragma unroll
    for (int q = 0; q < 8; q++) acc[q] = 0.0f;

    if (hf == 0)                                // self term on the even half only
        acc_row16(acc, H16[(size_t)w * 16 + sub]);

    for (int j0 = 0; j0 < cnt; j0 += 32) {
        int s = 0;
        if (j0 + lane < cnt) s = g_edst[base + j0 + lane];
        int m = cnt - j0; if (m > 32) m = 32;
        int tmax = (m + 1) >> 1;
        #pragma unroll 4
        for (int t = 0; t < tmax; t++) {
            int src = 2 * t + hf;
            int sv = __shfl_sync(0xffffffffu, s, src);
            uint4 v = H16[(size_t)sv * 16 + sub];   // sv==0 safe when invalid
            if (j0 + src < cnt) acc_row16(acc, v);
        }
    }

    #pragma unroll
    for (int q = 0; q < 8; q++)
        acc[q] += __shfl_xor_sync(0xffffffffu, acc[q], 16);

    if (hf == 0) {
        union { uint4 u; __half2 h[4]; } pk;
        #pragma unroll
        for (int q = 0; q < 4; q++)
            pk.h[q] = __floats2half2_rn(acc[2 * q], acc[2 * q + 1]);
        ((uint4*)g_T)[(size_t)w * 16 + sub] = pk.u;   // fp16 row, 256B
    }
}

// ---------------- shared mma core: Cs = A(TxW) for one 128x128 tile ----------------
__device__ __forceinline__ void mma_tile(char* smx, int row0, int nrows, int tid) {
    __half* As = (__half*)(smx + SM_AS);
    float*  Cs = (float*)(smx + SM_CS);

    const uint4* Tp = (const uint4*)g_T;
    for (int i = tid; i < 128 * 16; i += 256) {
        int r = i >> 4, ch = i & 15;
        int row = row0 + r;
        uint4 v = make_uint4(0, 0, 0, 0);
        if (row < nrows) v = Tp[(size_t)row * 16 + ch];
        *(uint4*)&As[r * 136 + ch * 8] = v;
    }
    __syncthreads();

    const int lane = tid & 31, warp = tid >> 5;
    const int m0 = warp * 16;
    float c[16][4];
    #pragma unroll
    for (int j = 0; j < 16; j++)
        #pragma unroll
        for (int q = 0; q < 4; q++) c[j][q] = 0.0f;

    unsigned a_base = (unsigned)__cvta_generic_to_shared(smx + SM_AS);
    unsigned b_base = (unsigned)__cvta_generic_to_shared(smx + SM_BS);
    unsigned a_addr = a_base + ((m0 + (lane & 15)) * 136 + (lane >> 4) * 8) * 2;

    #pragma unroll
    for (int k0 = 0; k0 < 128; k0 += 16) {
        unsigned a[4];
        ldsm_x4(a, a_addr + k0 * 2);
        unsigned brow = b_base + ((k0 + (lane & 15)) * 136) * 2;
        #pragma unroll
        for (int j = 0; j < 16; j++) {
            unsigned b[2];
            ldsm_x2_trans(b, brow + j * 16);
            mma16816(c[j], a, b);
        }
    }

    const int r1 = m0 + (lane >> 2);
    const int cb = 2 * (lane & 3);
    #pragma unroll
    for (int j = 0; j < 16; j++) {
        *(float2*)&Cs[r1 * 132 + j * 8 + cb]       = make_float2(c[j][0], c[j][1]);
        *(float2*)&Cs[(r1 + 8) * 132 + j * 8 + cb] = make_float2(c[j][2], c[j][3]);
    }
    __syncthreads();
}

// ---------------- GEMM 1: (half*)g_S = relu(dinv * (T @ W1) + b1) * dinv ----------------
__global__ __launch_bounds__(256)
void k_gemm_hs(const float* __restrict__ W, const float* __restrict__ bias, int nrows) {
    extern __shared__ char smx[];
    __half* Bs = (__half*)(smx + SM_BS);
    float*  Cs = (float*)(smx + SM_CS);
    const int tid  = threadIdx.x;
    const int row0 = blockIdx.x * 128;

    for (int i = tid; i < 128 * 32; i += 256) {
        int k = i >> 5, c4 = (i & 31) * 4;
        float4 w = *(const float4*)&W[k * 128 + c4];
        *(__half2*)&Bs[k * 136 + c4]     = __floats2half2_rn(w.x, w.y);
        *(__half2*)&Bs[k * 136 + c4 + 2] = __floats2half2_rn(w.z, w.w);
    }
    mma_tile(smx, row0, nrows, tid);

    const int tx = tid & 15, ty = tid >> 4, col = tx * 8;
    #pragma unroll
    for (int i = 0; i < 8; i++) {
        int row = row0 + ty * 8 + i;
        if (row < nrows) {
            float d = g_dinv[row];
            float4 v0 = *(float4*)&Cs[(ty * 8 + i) * 132 + col];
            float4 v1 = *(float4*)&Cs[(ty * 8 + i) * 132 + col + 4];
            float o[8] = {v0.x, v0.y, v0.z, v0.w, v1.x, v1.y, v1.z, v1.w};
            #pragma unroll
            for (int j = 0; j < 8; j++)
                o[j] = fmaxf(fmaf(o[j], d, bias[col + j]), 0.0f) * d;
            union { __half2 h[4]; uint4 u; } pk;
            pk.h[0] = __floats2half2_rn(o[0], o[1]);
            pk.h[1] = __floats2half2_rn(o[2], o[3]);
            pk.h[2] = __floats2half2_rn(o[4], o[5]);
            pk.h[3] = __floats2half2_rn(o[6], o[7]);
            *(uint4*)((__half*)g_S + (size_t)row * 128 + col) = pk.u;
        }
    }
}

// ---------------- GEMM 2: [mu | logvar] = dinv * (T @ [Wmu|Wlv]) + [bmu|blv] ----------------
__global__ __launch_bounds__(256)
void k_gemm_out(const float* __restrict__ Wmu, const float* __restrict__ Wlv,
                const float* __restrict__ bmu, const float* __restrict__ blv,
                float* __restrict__ out_mu, float* __restrict__ out_lv, int nrows) {
    extern __shared__ char smx[];
    __half* Bs = (__half*)(smx + SM_BS);
    float*  Cs = (float*)(smx + SM_CS);
    const int tid  = threadIdx.x;
    const int row0 = blockIdx.x * 128;

    for (int i = tid; i < 128 * 32; i += 256) {
        int k = i >> 5, c4 = (i & 31) * 4;
        float4 w = (c4 < 64) ? *(const float4*)&Wmu[k * 64 + c4]
                             : *(const float4*)&Wlv[k * 64 + (c4 - 64)];
        *(__half2*)&Bs[k * 136 + c4]     = __floats2half2_rn(w.x, w.y);
        *(__half2*)&Bs[k * 136 + c4 + 2] = __floats2half2_rn(w.z, w.w);
    }
    mma_tile(smx, row0, nrows, tid);

    const int tx = tid & 15, ty = tid >> 4, col = tx * 8;
    const bool is_mu = (col < 64);
    const float* bias = is_mu ? bmu : blv;
    float* outp = is_mu ? out_mu : out_lv;
    const int ocol = is_mu ? col : (col - 64);

    #pragma unroll
    for (int i = 0; i < 8; i++) {
        int row = row0 + ty * 8 + i;
        if (row < nrows) {
            float d = g_dinv[row];
            float4 v0 = *(float4*)&Cs[(ty * 8 + i) * 132 + col];
            float4 v1 = *(float4*)&Cs[(ty * 8 + i) * 132 + col + 4];
            float o[8] = {v0.x, v0.y, v0.z, v0.w, v1.x, v1.y, v1.z, v1.w};
            #pragma unroll
            for (int j = 0; j < 8; j++)
                o[j] = fmaf(o[j], d, bias[ocol + j]);
            float4* Op = (float4*)&outp[(size_t)row * 64 + ocol];
            Op[0] = make_float4(o[0], o[1], o[2], o[3]);
            Op[1] = make_float4(o[4], o[5], o[6], o[7]);
        }
    }
}

// ---------------- launch ----------------
extern "C" void kernel_launch(void* const* d_in, const int* in_sizes, int n_in,
                              void* d_out, int out_size) {
    const float* x   = (const float*)d_in[0];
    const void*  ei  = d_in[1];
    const float* W1  = (const float*)d_in[2];
    const float* b1  = (const float*)d_in[3];
    const float* Wmu = (const float*)d_in[4];
    const float* bmu = (const float*)d_in[5];
    const float* Wlv = (const float*)d_in[6];
    const float* blv = (const float*)d_in[7];
    float* out = (float*)d_out;

    const int n = in_sizes[0] / DF;     // 100000
    const int E = in_sizes[1] / 2;      // 1600000

    cudaFuncSetAttribute(k_gemm_hs,  cudaFuncAttributeMaxDynamicSharedMemorySize, SM_TOTAL);
    cudaFuncSetAttribute(k_gemm_out, cudaFuncAttributeMaxDynamicSharedMemorySize, SM_TOTAL);

    // CSR build (per call; kernel_launch must be self-contained & deterministic)
    k_init_detect<<<(n + 255) / 256, 256>>>((const long long*)ei, n, E);
    k_count<<<(E + 255) / 256, 256>>>(ei, E);
    k_alloc_prep<<<(n * 32 + 255) / 256, 256>>>(x, n);
    k_fill<<<(E + 255) / 256, 256>>>(E);

    const int gwblocks = (n * 32 + 255) / 256;   // one warp per node
    const int gblocks  = (n + 127) / 128;

    // Layer 1: T16 = Aggr(H); S(half) = relu(dinv*(T@W1)+b1)*dinv
    k_gather<<<gwblocks, 256>>>(n);
    k_gemm_hs<<<gblocks, 256, SM_TOTAL>>>(W1, b1, n);

    // Layers 2+3 share one aggregation; fused [Wmu|Wlv] GEMM writes mu and logvar
    k_gather<<<gwblocks, 256>>>(n);
    k_gemm_out<<<gblocks, 256, SM_TOTAL>>>(Wmu, Wlv, bmu, blv, out, out + (size_t)n * 64, n);
}

// round 15
// speedup vs baseline: 1.4967x; 1.4381x over previous
#include <cuda_runtime.h>
#include <cuda_fp16.h>
#include <cstdint>

#define NN 100000
#define DF 128
#define MAXE 1600000

// ---------------- device scratch: FROZEN symbol set/sizes/order (guard-sensitive).
//   g_S : (half*)g_S = prescaled feature rows (pass1: x*dinv, pass2: S from GEMM1)
//   g_T : (int2*)g_T = staged decoded edges during CSR build;
//         (half*)g_T = fp16 aggregation result afterwards
//   g_esrc[0..NN) = CSR offset cursor (end-of-range after fill); g_esrc[NN] = alloc counter
//   g_edst[0..E)  = CSR source-index list bucketed by destination
static __device__ float g_S[(size_t)NN * DF];
static __device__ float g_T[(size_t)NN * DF];
static __device__ float g_deg[NN];
static __device__ float g_dinv[NN];
static __device__ int   g_esrc[MAXE];
static __device__ int   g_edst[MAXE];
static __device__ int   g_mode;                 // 0 = edges are int64, 1 = int32

// ---------------- mma helpers ----------------
__device__ __forceinline__ void ldsm_x4(unsigned* r, unsigned addr) {
    asm volatile("ldmatrix.sync.aligned.m8n8.x4.shared.b16 {%0,%1,%2,%3}, [%4];"
                 : "=r"(r[0]), "=r"(r[1]), "=r"(r[2]), "=r"(r[3]) : "r"(addr));
}
__device__ __forceinline__ void ldsm_x2_trans(unsigned* r, unsigned addr) {
    asm volatile("ldmatrix.sync.aligned.m8n8.x2.trans.shared.b16 {%0,%1}, [%2];"
                 : "=r"(r[0]), "=r"(r[1]) : "r"(addr));
}
__device__ __forceinline__ void mma16816(float* c, const unsigned* a, const unsigned* b) {
    asm volatile("mma.sync.aligned.m16n8k16.row.col.f32.f16.f16.f32 "
                 "{%0,%1,%2,%3}, {%4,%5,%6,%7}, {%8,%9}, {%0,%1,%2,%3};"
                 : "+f"(c[0]), "+f"(c[1]), "+f"(c[2]), "+f"(c[3])
                 : "r"(a[0]), "r"(a[1]), "r"(a[2]), "r"(a[3]), "r"(b[0]), "r"(b[1]));
}

// smem layout (bytes): As 128x136 half | Bs 128x136 half; Cs (128x132 f32 = 67584B)
// OVERLAPS As+Bs after the mma loop (fragments are register-resident across the sync).
#define SM_AS 0
#define SM_BS 34816
#define SM_CS 0
#define SM_TOTAL 69632

// ---------------- edge decode helper ----------------
__device__ __forceinline__ void decode_edge(const void* ei, int E, int i, int& s, int& d) {
    if (g_mode) {
        const int* p = (const int*)ei;
        s = p[i]; d = p[(size_t)E + i];
    } else {
        const long long* p = (const long long*)ei;
        s = (int)p[i]; d = (int)p[(size_t)E + i];
    }
}

// ---------------- setup / CSR build (R10 structure) ----------------
__global__ void k_init_deg(int n) {
    int i = blockIdx.x * blockDim.x + threadIdx.x;
    if (i < n) g_deg[i] = 1.0f;                 // self loop contributes 1
    if (i == 0) g_esrc[NN] = 0;                 // allocation counter
}

__global__ void k_detect(const long long* __restrict__ ei, int n, int E) {
    __shared__ int flag;
    if (threadIdx.x == 0) flag = 0;
    __syncthreads();
    int m = min(1024, E);
    for (int i = threadIdx.x; i < m; i += blockDim.x) {
        long long v = ei[i];
        if (v < 0 || v >= (long long)n) flag = 1;
    }
    __syncthreads();
    if (threadIdx.x == 0) g_mode = flag;
}

// count + stage decoded (s,d) pairs into g_T (free until gather pass 1)
__global__ void k_count(const void* __restrict__ ei, int E) {
    int i = blockIdx.x * blockDim.x + threadIdx.x;
    if (i >= E) return;
    int s, d;
    decode_edge(ei, E, i, s, d);
    ((int2*)g_T)[i] = make_int2(s, d);
    atomicAdd(&g_deg[d], 1.0f);
}

__global__ void k_alloc(int n) {
    int i = blockIdx.x * blockDim.x + threadIdx.x;
    if (i >= n) return;
    float deg = g_deg[i];
    int c = (int)deg - 1;                       // in-degree without self loop
    g_esrc[i] = atomicAdd(&g_esrc[NN], c);      // disjoint ranges; order irrelevant
    g_dinv[i] = rsqrtf(deg);
}

__global__ void k_fill(int E) {
    int i = blockIdx.x * blockDim.x + threadIdx.x;
    if (i >= E) return;
    int2 e = ((const int2*)g_T)[i];             // staged by k_count
    int pos = atomicAdd(&g_esrc[e.y], 1);       // cursor ends at range end
    g_edst[pos] = e.x;
}

// ---------------- prep: (half*)g_S[row] = x[row] * dinv[row] ----------------
__global__ void k_prep(const float* __restrict__ x, int n) {
    int i = blockIdx.x * blockDim.x + threadIdx.x;   // n*32 float4 chunks
    if (i >= n * 32) return;
    int row = i >> 5;
    float4 v = ((const float4*)x)[i];
    float dv = g_dinv[row];
    __half2 h0 = __floats2half2_rn(v.x * dv, v.y * dv);
    __half2 h1 = __floats2half2_rn(v.z * dv, v.w * dv);
    ((__half2*)g_S)[(size_t)i * 2]     = h0;
    ((__half2*)g_S)[(size_t)i * 2 + 1] = h1;
}

// ---------------- gather: T16[v] = H[v] + sum_{s in N(v)} H[s];  H = (half*)g_S ----------
// R10 pair-split version: lanes 0-15 even neighbors, 16-31 odd; 16B per lane.
__device__ __forceinline__ void acc_row16(float* acc, uint4 v) {
    union { uint4 u; __half2 h[4]; } cv; cv.u = v;
    #pragma unroll
    for (int q = 0; q < 4; q++) {
        float2 f = __half22float2(cv.h[q]);
        acc[2 * q]     += f.x;
        acc[2 * q + 1] += f.y;
    }
}

__global__ void k_gather(int n) {
    int w = (blockIdx.x * blockDim.x + threadIdx.x) >> 5;
    if (w >= n) return;
    const int lane = threadIdx.x & 31;
    const int hf   = lane >> 4;                 // 0: even neighbors, 1: odd
    const int sub  = lane & 15;                 // 16B chunk within row
    const int cnt  = (int)g_deg[w] - 1;
    const int base = g_esrc[w] - cnt;           // cursor was advanced to end
    const uint4* H16 = (const uint4*)g_S;       // row = 16 uint4

    float acc[8];
    #pragma unroll
    for (int q = 0; q < 8; q++) acc[q] = 0.0f;

    if (hf == 0)                                // self term on the even half only
        acc_row16(acc, H16[(size_t)w * 16 + sub]);

    for (int j0 = 0; j0 < cnt; j0 += 32) {
        int s = 0;
        if (j0 + lane < cnt) s = g_edst[base + j0 + lane];
        int m = cnt - j0; if (m > 32) m = 32;
        int tmax = (m + 1) >> 1;
        #pragma unroll 4
        for (int t = 0; t < tmax; t++) {
            int src = 2 * t + hf;
            int sv = __shfl_sync(0xffffffffu, s, src);
            uint4 v = H16[(size_t)sv * 16 + sub];   // sv==0 safe when invalid
            if (j0 + src < cnt) acc_row16(acc, v);
        }
    }

    #pragma unroll
    for (int q = 0; q < 8; q++)
        acc[q] += __shfl_xor_sync(0xffffffffu, acc[q], 16);

    if (hf == 0) {
        union { uint4 u; __half2 h[4]; } pk;
        #pragma unroll
        for (int q = 0; q < 4; q++)
            pk.h[q] = __floats2half2_rn(acc[2 * q], acc[2 * q + 1]);
        ((uint4*)g_T)[(size_t)w * 16 + sub] = pk.u;   // fp16 row, 256B
    }
}

// ---------------- shared mma core: Cs = A(TxW) for one 128x128 tile ----------------
// Cs overlaps As/Bs: extra __syncthreads after the mma loop, fragments stay in regs.
__device__ __forceinline__ void mma_tile(char* smx, int row0, int nrows, int tid) {
    __half* As = (__half*)(smx + SM_AS);
    float*  Cs = (float*)(smx + SM_CS);

    const uint4* Tp = (const uint4*)g_T;
    for (int i = tid; i < 128 * 16; i += 256) {
        int r = i >> 4, ch = i & 15;
        int row = row0 + r;
        uint4 v = make_uint4(0, 0, 0, 0);
        if (row < nrows) v = Tp[(size_t)row * 16 + ch];
        *(uint4*)&As[r * 136 + ch * 8] = v;
    }
    __syncthreads();

    const int lane = tid & 31, warp = tid >> 5;
    const int m0 = warp * 16;
    float c[16][4];
    #pragma unroll
    for (int j = 0; j < 16; j++)
        #pragma unroll
        for (int q = 0; q < 4; q++) c[j][q] = 0.0f;

    unsigned a_base = (unsigned)__cvta_generic_to_shared(smx + SM_AS);
    unsigned b_base = (unsigned)__cvta_generic_to_shared(smx + SM_BS);
    unsigned a_addr = a_base + ((m0 + (lane & 15)) * 136 + (lane >> 4) * 8) * 2;

    #pragma unroll
    for (int k0 = 0; k0 < 128; k0 += 16) {
        unsigned a[4];
        ldsm_x4(a, a_addr + k0 * 2);
        unsigned brow = b_base + ((k0 + (lane & 15)) * 136) * 2;
        #pragma unroll
        for (int j = 0; j < 16; j++) {
            unsigned b[2];
            ldsm_x2_trans(b, brow + j * 16);
            mma16816(c[j], a, b);
        }
    }
    __syncthreads();                            // all ldsm reads done before Cs overwrite

    const int r1 = m0 + (lane >> 2);
    const int cb = 2 * (lane & 3);
    #pragma unroll
    for (int j = 0; j < 16; j++) {
        *(float2*)&Cs[r1 * 132 + j * 8 + cb]       = make_float2(c[j][0], c[j][1]);
        *(float2*)&Cs[(r1 + 8) * 132 + j * 8 + cb] = make_float2(c[j][2], c[j][3]);
    }
    __syncthreads();
}

// ---------------- GEMM 1: (half*)g_S = relu(dinv * (T @ W1) + b1) * dinv ----------------
__global__ __launch_bounds__(256)
void k_gemm_hs(const float* __restrict__ W, const float* __restrict__ bias, int nrows) {
    extern __shared__ char smx[];
    __half* Bs = (__half*)(smx + SM_BS);
    float*  Cs = (float*)(smx + SM_CS);
    const int tid  = threadIdx.x;
    const int row0 = blockIdx.x * 128;

    for (int i = tid; i < 128 * 32; i += 256) {
        int k = i >> 5, c4 = (i & 31) * 4;
        float4 w = *(const float4*)&W[k * 128 + c4];
        *(__half2*)&Bs[k * 136 + c4]     = __floats2half2_rn(w.x, w.y);
        *(__half2*)&Bs[k * 136 + c4 + 2] = __floats2half2_rn(w.z, w.w);
    }
    mma_tile(smx, row0, nrows, tid);

    const int tx = tid & 15, ty = tid >> 4, col = tx * 8;
    #pragma unroll
    for (int i = 0; i < 8; i++) {
        int row = row0 + ty * 8 + i;
        if (row < nrows) {
            float d = g_dinv[row];
            float4 v0 = *(float4*)&Cs[(ty * 8 + i) * 132 + col];
            float4 v1 = *(float4*)&Cs[(ty * 8 + i) * 132 + col + 4];
            float o[8] = {v0.x, v0.y, v0.z, v0.w, v1.x, v1.y, v1.z, v1.w};
            #pragma unroll
            for (int j = 0; j < 8; j++)
                o[j] = fmaxf(fmaf(o[j], d, bias[col + j]), 0.0f) * d;
            union { __half2 h[4]; uint4 u; } pk;
            pk.h[0] = __floats2half2_rn(o[0], o[1]);
            pk.h[1] = __floats2half2_rn(o[2], o[3]);
            pk.h[2] = __floats2half2_rn(o[4], o[5]);
            pk.h[3] = __floats2half2_rn(o[6], o[7]);
            *(uint4*)((__half*)g_S + (size_t)row * 128 + col) = pk.u;
        }
    }
}

// ---------------- GEMM 2: [mu | logvar] = dinv * (T @ [Wmu|Wlv]) + [bmu|blv] ----------------
__global__ __launch_bounds__(256)
void k_gemm_out(const float* __restrict__ Wmu, const float* __restrict__ Wlv,
                const float* __restrict__ bmu, const float* __restrict__ blv,
                float* __restrict__ out_mu, float* __restrict__ out_lv, int nrows) {
    extern __shared__ char smx[];
    __half* Bs = (__half*)(smx + SM_BS);
    float*  Cs = (float*)(smx + SM_CS);
    const int tid  = threadIdx.x;
    const int row0 = blockIdx.x * 128;

    for (int i = tid; i < 128 * 32; i += 256) {
        int k = i >> 5, c4 = (i & 31) * 4;
        float4 w = (c4 < 64) ? *(const float4*)&Wmu[k * 64 + c4]
                             : *(const float4*)&Wlv[k * 64 + (c4 - 64)];
        *(__half2*)&Bs[k * 136 + c4]     = __floats2half2_rn(w.x, w.y);
        *(__half2*)&Bs[k * 136 + c4 + 2] = __floats2half2_rn(w.z, w.w);
    }
    mma_tile(smx, row0, nrows, tid);

    const int tx = tid & 15, ty = tid >> 4, col = tx * 8;
    const bool is_mu = (col < 64);
    const float* bias = is_mu ? bmu : blv;
    float* outp = is_mu ? out_mu : out_lv;
    const int ocol = is_mu ? col : (col - 64);

    #pragma unroll
    for (int i = 0; i < 8; i++) {
        int row = row0 + ty * 8 + i;
        if (row < nrows) {
            float d = g_dinv[row];
            float4 v0 = *(float4*)&Cs[(ty * 8 + i) * 132 + col];
            float4 v1 = *(float4*)&Cs[(ty * 8 + i) * 132 + col + 4];
            float o[8] = {v0.x, v0.y, v0.z, v0.w, v1.x, v1.y, v1.z, v1.w};
            #pragma unroll
            for (int j = 0; j < 8; j++)
                o[j] = fmaf(o[j], d, bias[ocol + j]);
            float4* Op = (float4*)&outp[(size_t)row * 64 + ocol];
            Op[0] = make_float4(o[0], o[1], o[2], o[3]);
            Op[1] = make_float4(o[4], o[5], o[6], o[7]);
        }
    }
}

// ---------------- launch ----------------
extern "C" void kernel_launch(void* const* d_in, const int* in_sizes, int n_in,
                              void* d_out, int out_size) {
    const float* x   = (const float*)d_in[0];
    const void*  ei  = d_in[1];
    const float* W1  = (const float*)d_in[2];
    const float* b1  = (const float*)d_in[3];
    const float* Wmu = (const float*)d_in[4];
    const float* bmu = (const float*)d_in[5];
    const float* Wlv = (const float*)d_in[6];
    const float* blv = (const float*)d_in[7];
    float* out = (float*)d_out;

    const int n = in_sizes[0] / DF;     // 100000
    const int E = in_sizes[1] / 2;      // 1600000

    cudaFuncSetAttribute(k_gemm_hs,  cudaFuncAttributeMaxDynamicSharedMemorySize, SM_TOTAL);
    cudaFuncSetAttribute(k_gemm_out, cudaFuncAttributeMaxDynamicSharedMemorySize, SM_TOTAL);

    // CSR build (per call; kernel_launch must be self-contained & deterministic)
    k_init_deg<<<(n + 255) / 256, 256>>>(n);
    k_detect<<<1, 256>>>((const long long*)ei, n, E);
    k_count<<<(E + 255) / 256, 256>>>(ei, E);
    k_alloc<<<(n + 255) / 256, 256>>>(n);
    k_fill<<<(E + 255) / 256, 256>>>(E);

    const int gwblocks = (n * 32 + 255) / 256;   // one warp per node
    const int gblocks  = (n + 127) / 128;

    // Layer 1: H = fp16(x * dinv); T16 = Aggr(H); S(half) = relu(dinv*(T@W1)+b1)*dinv
    k_prep<<<(n * 32 + 255) / 256, 256>>>(x, n);
    k_gather<<<gwblocks, 256>>>(n);
    k_gemm_hs<<<gblocks, 256, SM_TOTAL>>>(W1, b1, n);

    // Layers 2+3 share one aggregation; fused [Wmu|Wlv] GEMM writes mu and logvar
    k_gather<<<gwblocks, 256>>>(n);
    k_gemm_out<<<gblocks, 256, SM_TOTAL>>>(Wmu, Wlv, bmu, blv, out, out + (size_t)n * 64, n);
}